// round 1
// baseline (speedup 1.0000x reference)
#include <cuda_runtime.h>

// Shapes (fixed by the dataset)
#define Bb 4
#define Qq 100
#define Cc 81
#define Mm 50
#define HW 65536

// Tiling
#define QT 64
#define MT 64
#define KC 32
#define SPLITK 128
#define KPB (HW / SPLITK)   // 512 k-elements per block

// -------- device scratch (no allocations allowed) --------
__device__ float g_xt[Bb * Qq * Mm];   // x . t
__device__ float g_st[Bb * Qq * Mm];   // sig(x) . t
__device__ float g_sp[Bb * Qq];        // sum softplus(x) per (b,q)
__device__ float g_sg[Bb * Qq];        // sum sigmoid(x) per (b,q)
__device__ float g_ts[Bb * Mm];        // sum t per (b,m)
__device__ int   g_id64;               // tgt_ids stored as int64?

// -------- init: zero scratch + detect id width --------
__global__ void init_k(const unsigned int* __restrict__ ids) {
    int i = blockIdx.x * blockDim.x + threadIdx.x;
    if (i < Bb * Qq * Mm) { g_xt[i] = 0.f; g_st[i] = 0.f; }
    if (i < Bb * Qq)      { g_sp[i] = 0.f; g_sg[i] = 0.f; }
    if (i < Bb * Mm)      { g_ts[i] = 0.f; }
    if (i == 0) {
        // If the 200 ids are int64, words come in (value, 0) pairs. Reading
        // only the first 200 32-bit words is in-bounds under either layout.
        int is64 = 1;
        for (int j = 0; j < (Bb * Mm) / 2; j++) {
            if (ids[2 * j + 1] != 0u) { is64 = 0; break; }
        }
        g_id64 = is64;
    }
}

// -------- main: fused convert + dual dot-product GEMM, split-K --------
__global__ __launch_bounds__(256)
void cost_main(const float* __restrict__ X, const float* __restrict__ T) {
    __shared__ float As[KC][QT + 4];   // x
    __shared__ float Ss[KC][QT + 4];   // sigmoid(x)
    __shared__ float Ts[KC][MT + 4];   // t

    const int tid   = threadIdx.x;
    const int split = blockIdx.x;
    const int qtile = blockIdx.y;
    const int b     = blockIdx.z;
    const int q0    = qtile * QT;
    const int kb    = split * KPB;

    const int lr = tid >> 3;          // 0..31 : row within 32-row load slab
    const int lc = (tid & 7) * 4;     // 0,4,...,28 : k offset (float4)
    const int ty = tid >> 4;          // 0..15
    const int tx = tid & 15;          // 0..15
    const int qb = ty * 4;
    const int mb = tx * 4;

    const float* Xb = X + (size_t)b * Qq * HW;
    const float* Tb = T + (size_t)b * Mm * HW;

    // 4q x 4m micro-tile as f32x2 pairs, for both dot products
    unsigned long long accx[2][4], accs[2][4];
#pragma unroll
    for (int p = 0; p < 2; p++)
#pragma unroll
        for (int j = 0; j < 4; j++) { accx[p][j] = 0ull; accs[p][j] = 0ull; }

    float spr[2] = {0.f, 0.f};   // softplus row partials (rows lr, lr+32)
    float sgr[2] = {0.f, 0.f};   // sigmoid row partials
    float tpr[2] = {0.f, 0.f};   // t row partials

    for (int kc = 0; kc < KPB; kc += KC) {
        const int k = kb + kc;
#pragma unroll
        for (int h = 0; h < 2; h++) {
            const int r  = lr + 32 * h;
            const int qg = q0 + r;
            const bool vq = (qg < Qq);
            float4 v = make_float4(0.f, 0.f, 0.f, 0.f);
            if (vq) v = *(const float4*)(Xb + (size_t)qg * HW + (k + lc));
            float xs[4] = {v.x, v.y, v.z, v.w};
            float sgv[4];
            float spl = 0.f, sgl = 0.f;
#pragma unroll
            for (int i = 0; i < 4; i++) {
                float xx  = xs[i];
                float e   = __expf(-fabsf(xx));            // exp(-|x|)
                float inv = __fdividef(1.0f, 1.0f + e);
                float sg  = (xx >= 0.f) ? inv : (1.0f - inv);
                spl += fmaxf(xx, 0.f) + __logf(1.0f + e);  // softplus(x)
                sgl += sg;
                sgv[i] = vq ? sg : 0.f;
            }
            if (vq) { spr[h] += spl; sgr[h] += sgl; }
#pragma unroll
            for (int i = 0; i < 4; i++) {
                As[lc + i][r] = xs[i];
                Ss[lc + i][r] = sgv[i];
            }
            // t row (m index == r)
            float4 w = make_float4(0.f, 0.f, 0.f, 0.f);
            if (r < Mm) {
                w = *(const float4*)(Tb + (size_t)r * HW + (k + lc));
                if (qtile == 0) tpr[h] += w.x + w.y + w.z + w.w;
            }
            Ts[lc + 0][r] = w.x; Ts[lc + 1][r] = w.y;
            Ts[lc + 2][r] = w.z; Ts[lc + 3][r] = w.w;
        }
        __syncthreads();

#pragma unroll
        for (int kk = 0; kk < KC; kk++) {
            const double2 ad = *(const double2*)&As[kk][qb];
            const double2 sd = *(const double2*)&Ss[kk][qb];
            const float4  bt = *(const float4*)&Ts[kk][mb];
            unsigned long long a01 = __double_as_longlong(ad.x);
            unsigned long long a23 = __double_as_longlong(ad.y);
            unsigned long long s01 = __double_as_longlong(sd.x);
            unsigned long long s23 = __double_as_longlong(sd.y);
            const float bf[4] = {bt.x, bt.y, bt.z, bt.w};
            unsigned long long bp[4];
#pragma unroll
            for (int j = 0; j < 4; j++) {
                unsigned int bbits = __float_as_uint(bf[j]);
                asm("mov.b64 %0, {%1, %1};" : "=l"(bp[j]) : "r"(bbits));
            }
#pragma unroll
            for (int j = 0; j < 4; j++) {
                asm("fma.rn.f32x2 %0, %1, %2, %0;" : "+l"(accx[0][j]) : "l"(a01), "l"(bp[j]));
                asm("fma.rn.f32x2 %0, %1, %2, %0;" : "+l"(accx[1][j]) : "l"(a23), "l"(bp[j]));
                asm("fma.rn.f32x2 %0, %1, %2, %0;" : "+l"(accs[0][j]) : "l"(s01), "l"(bp[j]));
                asm("fma.rn.f32x2 %0, %1, %2, %0;" : "+l"(accs[1][j]) : "l"(s23), "l"(bp[j]));
            }
        }
        __syncthreads();
    }

    // Reduce row partials across the 8 lanes that share each load row.
#pragma unroll
    for (int off = 4; off; off >>= 1) {
        spr[0] += __shfl_down_sync(0xffffffffu, spr[0], off);
        spr[1] += __shfl_down_sync(0xffffffffu, spr[1], off);
        sgr[0] += __shfl_down_sync(0xffffffffu, sgr[0], off);
        sgr[1] += __shfl_down_sync(0xffffffffu, sgr[1], off);
        tpr[0] += __shfl_down_sync(0xffffffffu, tpr[0], off);
        tpr[1] += __shfl_down_sync(0xffffffffu, tpr[1], off);
    }
    if ((tid & 7) == 0) {
#pragma unroll
        for (int h = 0; h < 2; h++) {
            int r  = lr + 32 * h;
            int qg = q0 + r;
            if (qg < Qq) {
                atomicAdd(&g_sp[b * Qq + qg], spr[h]);
                atomicAdd(&g_sg[b * Qq + qg], sgr[h]);
            }
            if (qtile == 0 && r < Mm) atomicAdd(&g_ts[b * Mm + r], tpr[h]);
        }
    }

    // Accumulate outputs (split-K partials)
#pragma unroll
    for (int p = 0; p < 2; p++) {
#pragma unroll
        for (int j = 0; j < 4; j++) {
            float xlo, xhi, slo, shi;
            asm("mov.b64 {%0, %1}, %2;" : "=f"(xlo), "=f"(xhi) : "l"(accx[p][j]));
            asm("mov.b64 {%0, %1}, %2;" : "=f"(slo), "=f"(shi) : "l"(accs[p][j]));
            int m = mb + j;
            if (m < Mm) {
                int ql = q0 + qb + 2 * p;
                if (ql < Qq) {
                    atomicAdd(&g_xt[(b * Qq + ql) * Mm + m], xlo);
                    atomicAdd(&g_st[(b * Qq + ql) * Mm + m], slo);
                }
                if (ql + 1 < Qq) {
                    atomicAdd(&g_xt[(b * Qq + ql + 1) * Mm + m], xhi);
                    atomicAdd(&g_st[(b * Qq + ql + 1) * Mm + m], shi);
                }
            }
        }
    }
}

// -------- finalize: softmax class cost + assemble C --------
__global__ void finalize_k(const float* __restrict__ logits,
                           const unsigned int* __restrict__ ids,
                           float* __restrict__ out) {
    const int bq = blockIdx.x;         // 0..B*Q-1
    const int b  = bq / Qq;
    const int tid = threadIdx.x;
    __shared__ float se[Cc];
    __shared__ float s_inv;
    if (tid < Cc) se[tid] = logits[bq * Cc + tid];
    __syncthreads();
    if (tid == 0) {
        float mx = se[0];
        for (int c = 1; c < Cc; c++) mx = fmaxf(mx, se[c]);
        float s = 0.f;
        for (int c = 0; c < Cc; c++) { float e = __expf(se[c] - mx); se[c] = e; s += e; }
        s_inv = __fdividef(1.0f, s);
    }
    __syncthreads();
    if (tid < Mm) {
        const int m = tid;
        unsigned id = g_id64 ? ids[2 * (b * Mm + m)] : ids[b * Mm + m];
        float prob   = se[id] * s_inv;
        float spmean = g_sp[bq] * (1.0f / (float)HW);
        float xt     = g_xt[bq * Mm + m];
        float st     = g_st[bq * Mm + m];
        float denom  = g_sg[bq] + g_ts[b * Mm + m] + 1e-6f;
        float cmask  = spmean - xt * (1.0f / (float)HW);
        float cdice  = 1.0f - 2.0f * st / denom;
        out[bq * Mm + m] = -prob + cmask + cdice;
    }
}

extern "C" void kernel_launch(void* const* d_in, const int* in_sizes, int n_in,
                              void* d_out, int out_size) {
    const float*        logits = (const float*)d_in[0];        // [B,Q,C]
    const float*        pmask  = (const float*)d_in[1];        // [B,Q,H,W]
    const unsigned int* ids    = (const unsigned int*)d_in[2]; // [B,M] (int32 or int64)
    const float*        tmask  = (const float*)d_in[3];        // [B,M,H,W]
    float*              out    = (float*)d_out;                // [B,Q,M]

    init_k<<<(Bb * Qq * Mm + 255) / 256, 256>>>(ids);
    dim3 grid(SPLITK, (Qq + QT - 1) / QT, Bb);
    cost_main<<<grid, 256>>>(pmask, tmask);
    finalize_k<<<Bb * Qq, 128>>>(logits, ids, out);
}

// round 3
// speedup vs baseline: 3.8044x; 3.8044x over previous
#include <cuda_runtime.h>
#include <cuda_bf16.h>
#include <cstdint>

// Shapes (fixed)
#define Bb  4
#define Qq  100
#define Cc  81
#define Mm  50
#define HWN 65536

// Tiling
#define SPL 36            // K-splits per batch; grid = 36 x 4 = 144 CTAs (1 wave)
#define KC  64            // k-elements per stage
#define PW  56            // padded partial row width in scratch

// Smem: rows stride 144B (36 words) -> conflict-free ldmatrix
#define RS     144
#define SS_OFF (128 * RS)          // Ss after 128 A rows
#define TS_OFF (2 * 128 * RS)      // Ts after Ss
#define STAGE  (2 * 128 * RS + 64 * RS)   // 46080 B
#define SMEM_BYTES (2 * STAGE)             // double buffered

// -------- device scratch (static; no allocations) --------
__device__ float g_px[(size_t)Bb * SPL * Qq * PW];   // per-split x.t partials
__device__ float g_ps[(size_t)Bb * SPL * Qq * PW];   // per-split sig(x).t partials
__device__ float g_spp[Bb * SPL * Qq];               // per-split softplus row sums
__device__ float g_sgp[Bb * SPL * Qq];               // per-split sigmoid row sums
__device__ float g_tsp[Bb * SPL * Mm];               // per-split t row sums

__device__ __forceinline__ uint32_t s2u(const void* p) {
    uint32_t a;
    asm("{ .reg .u64 t; cvta.to.shared.u64 t, %1; cvt.u32.u64 %0, t; }" : "=r"(a) : "l"(p));
    return a;
}
__device__ __forceinline__ void ldsm4(uint32_t* r, uint32_t a) {
    asm volatile("ldmatrix.sync.aligned.m8n8.x4.shared.b16 {%0,%1,%2,%3}, [%4];"
                 : "=r"(r[0]), "=r"(r[1]), "=r"(r[2]), "=r"(r[3]) : "r"(a));
}
__device__ __forceinline__ void mma16816(float* c, const uint32_t* a, uint32_t b0, uint32_t b1) {
    asm volatile("mma.sync.aligned.m16n8k16.row.col.f32.bf16.bf16.f32 "
                 "{%0,%1,%2,%3}, {%4,%5,%6,%7}, {%8,%9}, {%0,%1,%2,%3};"
                 : "+f"(c[0]), "+f"(c[1]), "+f"(c[2]), "+f"(c[3])
                 : "r"(a[0]), "r"(a[1]), "r"(a[2]), "r"(a[3]), "r"(b0), "r"(b1));
}

// ================= fused convert + dual bf16 mma.sync GEMM =================
__global__ __launch_bounds__(256, 1)
void cost_main(const float* __restrict__ X, const float* __restrict__ T) {
    extern __shared__ char smem[];
    const uint32_t sm0 = s2u(smem);

    const int tid = threadIdx.x;
    const int l   = tid & 31;
    const int wid = tid >> 5;
    const int wr  = wid >> 1;          // warp row 0..3  (32 q-rows each)
    const int wc  = wid & 1;           // warp col 0..1  (32 m-cols each)
    const int rb  = tid >> 4;          // 0..15 load row
    const int cg  = tid & 15;          // 0..15 column group (4 floats)

    const int split = blockIdx.x;
    const int b     = blockIdx.y;
    const int nst   = (split < 16) ? 29 : 28;
    const int k0    = (split * 28 + min(split, 16)) * KC;

    const float* Xb = X + (size_t)b * Qq * HWN;
    const float* Tb = T + (size_t)b * Mm * HWN;

    // ldmatrix per-lane addresses (canonical m8n8.x4 patterns)
    const uint32_t sA0 = sm0 + (uint32_t)(wr * 32 + (l & 15)) * RS + ((l >> 4) & 1) * 16;
    const uint32_t sA1 = sA0 + 16 * RS;
    const uint32_t sS0 = sA0 + SS_OFF;
    const uint32_t sS1 = sA1 + SS_OFF;
    const uint32_t sB0 = sm0 + TS_OFF +
        (uint32_t)(wc * 32 + (l & 7) + ((l >> 4) & 1) * 8) * RS + ((l >> 3) & 1) * 16;
    const uint32_t sB1 = sB0 + 16 * RS;

    float accx[2][4][4], accs[2][4][4];
#pragma unroll
    for (int i = 0; i < 2; i++)
#pragma unroll
        for (int j = 0; j < 4; j++)
#pragma unroll
            for (int k = 0; k < 4; k++) { accx[i][j][k] = 0.f; accs[i][j][k] = 0.f; }

    float sp_acc[7] = {0,0,0,0,0,0,0};
    float sg_acc[7] = {0,0,0,0,0,0,0};
    float ts_acc[4] = {0,0,0,0};

    float4 rx[7], rt[4];
    // prologue: prefetch stage 0
    {
        const int kg = k0 + 4 * cg;
#pragma unroll
        for (int i = 0; i < 7; i++) {
            const int r = rb + 16 * i;
            if (r < Qq) rx[i] = *(const float4*)(Xb + (size_t)r * HWN + kg);
        }
#pragma unroll
        for (int i = 0; i < 4; i++) {
            const int r = rb + 16 * i;
            if (r < Mm) rt[i] = *(const float4*)(Tb + (size_t)r * HWN + kg);
        }
    }

    for (int s = 0; s < nst; s++) {
        const int buf = s & 1;
        char* const bufp = smem + buf * STAGE;

        // ---- convert staged regs -> bf16 smem ----
#pragma unroll
        for (int i = 0; i < 7; i++) {
            const int r = rb + 16 * i;
            if (r < Qq) {
                const float xs[4] = {rx[i].x, rx[i].y, rx[i].z, rx[i].w};
                float sg[4];
#pragma unroll
                for (int j = 0; j < 4; j++) {
                    const float xx = xs[j];
                    float th;
                    asm("tanh.approx.f32 %0, %1;" : "=f"(th) : "f"(0.5f * xx));
                    const float sv = fmaf(0.5f, th, 0.5f);
                    sg[j] = sv;
                    sg_acc[i] += sv;
                    sp_acc[i] += fmaxf(xx, 0.f) - __logf(fmaf(0.5f, fabsf(th), 0.5f));
                }
                __nv_bfloat162 hx0 = __float22bfloat162_rn(make_float2(xs[0], xs[1]));
                __nv_bfloat162 hx1 = __float22bfloat162_rn(make_float2(xs[2], xs[3]));
                __nv_bfloat162 hs0 = __float22bfloat162_rn(make_float2(sg[0], sg[1]));
                __nv_bfloat162 hs1 = __float22bfloat162_rn(make_float2(sg[2], sg[3]));
                char* const p = bufp + r * RS + cg * 8;
                *reinterpret_cast<uint2*>(p) =
                    make_uint2(*reinterpret_cast<uint32_t*>(&hx0), *reinterpret_cast<uint32_t*>(&hx1));
                *reinterpret_cast<uint2*>(p + SS_OFF) =
                    make_uint2(*reinterpret_cast<uint32_t*>(&hs0), *reinterpret_cast<uint32_t*>(&hs1));
            }
        }
#pragma unroll
        for (int i = 0; i < 4; i++) {
            const int r = rb + 16 * i;
            if (r < Mm) {
                const float4 w = rt[i];
                ts_acc[i] += w.x + w.y + w.z + w.w;
                __nv_bfloat162 h0 = __float22bfloat162_rn(make_float2(w.x, w.y));
                __nv_bfloat162 h1 = __float22bfloat162_rn(make_float2(w.z, w.w));
                *reinterpret_cast<uint2*>(bufp + TS_OFF + r * RS + cg * 8) =
                    make_uint2(*reinterpret_cast<uint32_t*>(&h0), *reinterpret_cast<uint32_t*>(&h1));
            }
        }

        // ---- prefetch next stage (in flight across the mma phase) ----
        if (s + 1 < nst) {
            const int kg = k0 + (s + 1) * KC + 4 * cg;
#pragma unroll
            for (int i = 0; i < 7; i++) {
                const int r = rb + 16 * i;
                if (r < Qq) rx[i] = *(const float4*)(Xb + (size_t)r * HWN + kg);
            }
#pragma unroll
            for (int i = 0; i < 4; i++) {
                const int r = rb + 16 * i;
                if (r < Mm) rt[i] = *(const float4*)(Tb + (size_t)r * HWN + kg);
            }
        }

        __syncthreads();

        // ---- dual mma over KC=64 (4 k16-steps) ----
        const uint32_t boff = (uint32_t)buf * STAGE;
#pragma unroll
        for (int st = 0; st < 4; st++) {
            const uint32_t so = boff + st * 32;
            uint32_t ax0[4], ax1[4], as0[4], as1[4], bb0[4], bb1[4];
            ldsm4(ax0, sA0 + so); ldsm4(ax1, sA1 + so);
            ldsm4(as0, sS0 + so); ldsm4(as1, sS1 + so);
            ldsm4(bb0, sB0 + so); ldsm4(bb1, sB1 + so);
            const uint32_t bfr[4][2] = {{bb0[0], bb0[1]}, {bb0[2], bb0[3]},
                                        {bb1[0], bb1[1]}, {bb1[2], bb1[3]}};
#pragma unroll
            for (int fc = 0; fc < 4; fc++) {
                mma16816(accx[0][fc], ax0, bfr[fc][0], bfr[fc][1]);
                mma16816(accx[1][fc], ax1, bfr[fc][0], bfr[fc][1]);
                mma16816(accs[0][fc], as0, bfr[fc][0], bfr[fc][1]);
                mma16816(accs[1][fc], as1, bfr[fc][0], bfr[fc][1]);
            }
        }
        // note: 2-buffer safety — any STS for stage s+2 happens after the
        // barrier of stage s+1, which is after every warp's mma of stage s.
    }

    // ---- row-sum reductions (16 lanes share a row) -> scratch ----
#pragma unroll
    for (int i = 0; i < 7; i++) {
        float v1 = sp_acc[i], v2 = sg_acc[i];
#pragma unroll
        for (int off = 8; off; off >>= 1) {
            v1 += __shfl_down_sync(0xffffffffu, v1, off, 16);
            v2 += __shfl_down_sync(0xffffffffu, v2, off, 16);
        }
        const int r = rb + 16 * i;
        if (cg == 0 && r < Qq) {
            g_spp[(b * SPL + split) * Qq + r] = v1;
            g_sgp[(b * SPL + split) * Qq + r] = v2;
        }
    }
#pragma unroll
    for (int i = 0; i < 4; i++) {
        float v = ts_acc[i];
#pragma unroll
        for (int off = 8; off; off >>= 1) v += __shfl_down_sync(0xffffffffu, v, off, 16);
        const int r = rb + 16 * i;
        if (cg == 0 && r < Mm) g_tsp[(b * SPL + split) * Mm + r] = v;
    }

    // ---- write mma partials to scratch ----
    {
        const size_t base = (size_t)(b * SPL + split) * Qq;
        const int ql = l >> 2;
        const int mo = 2 * (l & 3);
#pragma unroll
        for (int fr = 0; fr < 2; fr++)
#pragma unroll
            for (int fc = 0; fc < 4; fc++) {
                const int m = wc * 32 + fc * 8 + mo;
                if (m < Mm) {
                    const int q = wr * 32 + fr * 16 + ql;
                    if (q < Qq) {
                        *(float2*)&g_px[(base + q) * PW + m] =
                            make_float2(accx[fr][fc][0], accx[fr][fc][1]);
                        *(float2*)&g_ps[(base + q) * PW + m] =
                            make_float2(accs[fr][fc][0], accs[fr][fc][1]);
                    }
                    if (q + 8 < Qq) {
                        *(float2*)&g_px[(base + q + 8) * PW + m] =
                            make_float2(accx[fr][fc][2], accx[fr][fc][3]);
                        *(float2*)&g_ps[(base + q + 8) * PW + m] =
                            make_float2(accs[fr][fc][2], accs[fr][fc][3]);
                    }
                }
            }
    }
}

// ================= finalize: reduce splits + softmax + assemble =================
__global__ __launch_bounds__(256)
void finalize_k(const float* __restrict__ logits,
                const unsigned int* __restrict__ ids,
                float* __restrict__ out) {
    const int bq = blockIdx.x;           // 0..B*Q-1
    const int b  = bq / Qq;
    const int q  = bq % Qq;
    const int tid = threadIdx.x;
    __shared__ float se[Cc];
    __shared__ float sinv, ssp, ssg;
    __shared__ float red_x[4][Mm], red_s[4][Mm], red_t[4][Mm];
    __shared__ int s64;

    if (tid == 0) s64 = 1;
    if (tid < Cc) se[tid] = logits[bq * Cc + tid];
    __syncthreads();
    if (tid < 100 && ids[2 * tid + 1] != 0u) s64 = 0;  // int64 high words all zero
    if (tid == 0) {
        float mx = se[0];
        for (int c = 1; c < Cc; c++) mx = fmaxf(mx, se[c]);
        float sm = 0.f;
        for (int c = 0; c < Cc; c++) { float e = __expf(se[c] - mx); se[c] = e; sm += e; }
        sinv = __fdividef(1.0f, sm);
    }
    // per-q softplus/sigmoid totals (warp 1)
    if (tid >= 32 && tid < 64) {
        const int ll = tid - 32;
        float vsp = 0.f, vsg = 0.f;
        for (int s = ll; s < SPL; s += 32) {
            vsp += g_spp[(b * SPL + s) * Qq + q];
            vsg += g_sgp[(b * SPL + s) * Qq + q];
        }
#pragma unroll
        for (int off = 16; off; off >>= 1) {
            vsp += __shfl_down_sync(0xffffffffu, vsp, off);
            vsg += __shfl_down_sync(0xffffffffu, vsg, off);
        }
        if (ll == 0) { ssp = vsp; ssg = vsg; }
    }
    // per-(q,m) partial sums over 36 splits, 4-way split-parallel
    {
        const int sc = tid >> 6, r = tid & 63;
        if (r < Mm) {
            float ax = 0.f, as_ = 0.f, at = 0.f;
            for (int s = sc; s < SPL; s += 4) {
                const size_t base = ((size_t)(b * SPL + s) * Qq + q) * PW + r;
                ax  += g_px[base];
                as_ += g_ps[base];
                at  += g_tsp[(b * SPL + s) * Mm + r];
            }
            red_x[sc][r] = ax; red_s[sc][r] = as_; red_t[sc][r] = at;
        }
    }
    __syncthreads();
    if (tid < Mm) {
        const int m = tid;
        const float ax  = red_x[0][m] + red_x[1][m] + red_x[2][m] + red_x[3][m];
        const float as_ = red_s[0][m] + red_s[1][m] + red_s[2][m] + red_s[3][m];
        const float at  = red_t[0][m] + red_t[1][m] + red_t[2][m] + red_t[3][m];
        const unsigned id = s64 ? ids[2 * (b * Mm + m)] : ids[b * Mm + m];
        const float prob  = se[id] * sinv;
        const float spm   = ssp * (1.0f / (float)HWN);
        const float denom = ssg + at + 1e-6f;
        out[bq * Mm + m] = -prob + (spm - ax * (1.0f / (float)HWN)) + 1.0f - 2.0f * as_ / denom;
    }
}

extern "C" void kernel_launch(void* const* d_in, const int* in_sizes, int n_in,
                              void* d_out, int out_size) {
    const float*        logits = (const float*)d_in[0];        // [B,Q,C]
    const float*        pmask  = (const float*)d_in[1];        // [B,Q,H,W]
    const unsigned int* ids    = (const unsigned int*)d_in[2]; // [B,M] int32 or int64
    const float*        tmask  = (const float*)d_in[3];        // [B,M,H,W]
    float*              out    = (float*)d_out;                // [B,Q,M]

    cudaFuncSetAttribute(cost_main, cudaFuncAttributeMaxDynamicSharedMemorySize, SMEM_BYTES);
    dim3 grid(SPL, Bb);
    cost_main<<<grid, 256, SMEM_BYTES>>>(pmask, tmask);
    finalize_k<<<Bb * Qq, 256>>>(logits, ids, out);
}